// round 14
// baseline (speedup 1.0000x reference)
#include <cuda_runtime.h>
#include <cuda_bf16.h>
#include <cstdint>

// ---------------------------------------------------------------------------
// Device-global scratch (allocation-free)
// ---------------------------------------------------------------------------
__device__ float g_a[12544];                     // attention scalar per pixel
__device__ float g_h1s[4][12544 * 64];           // per-split layer-1 partials
__device__ int   g_cnt[392];                     // per-m-tile arrival counters (zero-init, self-resetting)
__device__ __align__(16) __nv_bfloat16 gW1hi[64 * 2048];  // [chunk][k32][n64]
__device__ __align__(16) __nv_bfloat16 gW1lo[64 * 2048];

// ---------------------------------------------------------------------------
// Helpers
// ---------------------------------------------------------------------------
__device__ __forceinline__ uint32_t smem_u32(const void* p) {
    return (uint32_t)__cvta_generic_to_shared(p);
}
__device__ __forceinline__ void ldsm4(uint32_t& r0, uint32_t& r1, uint32_t& r2, uint32_t& r3, uint32_t a) {
    asm volatile("ldmatrix.sync.aligned.m8n8.x4.shared.b16 {%0,%1,%2,%3},[%4];"
                 : "=r"(r0), "=r"(r1), "=r"(r2), "=r"(r3) : "r"(a));
}
__device__ __forceinline__ void ldsm4t(uint32_t& r0, uint32_t& r1, uint32_t& r2, uint32_t& r3, uint32_t a) {
    asm volatile("ldmatrix.sync.aligned.m8n8.x4.trans.shared.b16 {%0,%1,%2,%3},[%4];"
                 : "=r"(r0), "=r"(r1), "=r"(r2), "=r"(r3) : "r"(a));
}
__device__ __forceinline__ void mma_bf16(float* c, const uint32_t* a, uint32_t b0, uint32_t b1) {
    asm volatile(
        "mma.sync.aligned.m16n8k16.row.col.f32.bf16.bf16.f32 "
        "{%0,%1,%2,%3},{%4,%5,%6,%7},{%8,%9},{%0,%1,%2,%3};"
        : "+f"(c[0]), "+f"(c[1]), "+f"(c[2]), "+f"(c[3])
        : "r"(a[0]), "r"(a[1]), "r"(a[2]), "r"(a[3]), "r"(b0), "r"(b1));
}
__device__ __forceinline__ uint32_t cvt_hi2(float f0, float f1) {
    uint32_t r;
    asm("cvt.rn.bf16x2.f32 %0, %1, %2;" : "=r"(r) : "f"(f1), "f"(f0));
    return r;
}
__device__ __forceinline__ uint32_t cvt_lo2(float f0, float f1, uint32_t hp) {
    float h0 = __uint_as_float(hp << 16);
    float h1 = __uint_as_float(hp & 0xFFFF0000u);
    return cvt_hi2(f0 - h0, f1 - h1);
}

// ---------------------------------------------------------------------------
// k0: split W1 into bf16 hi/lo  (blocks 0..511)  +  zero out  (512..639)
// ---------------------------------------------------------------------------
__global__ void __launch_bounds__(256) k0_convW(const float* __restrict__ W1,
                                               float* __restrict__ out) {
    if (blockIdx.x < 512) {
        int i = blockIdx.x * 256 + threadIdx.x;       // 131072 elems
        int k = i >> 6, n = i & 63;
        int chunk = k >> 5, kk = k & 31;
        float w = W1[i];
        __nv_bfloat16 h = __float2bfloat16_rn(w);
        int o = chunk * 2048 + kk * 64 + n;
        gW1hi[o] = h;
        gW1lo[o] = __float2bfloat16_rn(w - __bfloat162float(h));
    } else {
        ((float4*)out)[(blockIdx.x - 512) * 256 + threadIdx.x] =
            make_float4(0.f, 0.f, 0.f, 0.f);
    }
}

// ---------------------------------------------------------------------------
// k1: split-K GEMM + fused last-block tail.
// grid 1568 = 392 m-tiles x 4 K-quarters.  Tile 32 px x 64 out, K-chunk 32,
// 128 threads, 4 warps m16 x n32.  Partials via plain STG; the 4th block to
// finish an m-tile sums the partials and runs the tail MLP for its 32 pixels.
// ---------------------------------------------------------------------------
#define APITCH 40
#define BPITCH 72
#define AHI 0
#define ALO 2560                  // 32*40*2
#define BHI 5120
#define BLO 9728                  // + 32*72*2
#define STG 14336

__global__ void __launch_bounds__(128) k1_gemm(
    const float* __restrict__ x,
    const float* __restrict__ b1,
    const float* __restrict__ W2, const float* __restrict__ b2,
    const float* __restrict__ W3, const float* __restrict__ b3,
    const float* __restrict__ W4, const float* __restrict__ b4)
{
    __shared__ __align__(16) char sStage[2][STG];   // 28672 B
    __shared__ int sIsLast;

    const int tid  = threadIdx.x;
    const int lane = tid & 31;
    const int warp = tid >> 5;
    const int wm16 = (warp >> 1) * 16;          // 0 or 16
    const int wn32 = (warp & 1) * 32;           // 0 or 32
    const int mtile  = blockIdx.x >> 2;
    const int m_base = mtile * 32;
    const int split  = blockIdx.x & 3;          // K quarter

    const int lkr = (lane & 7) + ((lane >> 3) & 1) * 8;   // 0..15
    const int lnc = (lane >> 4) * 8;                       // 0 or 8

    const int a_row = tid >> 2;                 // 0..31
    const int a_kq  = (tid & 3) * 8;            // k offset {0,8,16,24}
    const int b_row = tid >> 2;                 // 0..31
    const int b_col = (tid & 3) * 16;           // n offset {0,16,32,48}

    float acc[4][4];
#pragma unroll
    for (int j = 0; j < 4; j++)
#pragma unroll
        for (int i = 0; i < 4; i++) acc[j][i] = 0.f;

    const float* aBase = x + (size_t)(m_base + a_row) * 2048 + split * 512 + a_kq;
    const __nv_bfloat16* whBase = gW1hi + (split * 16) * 2048 + b_row * 64 + b_col;
    const __nv_bfloat16* wlBase = gW1lo + (split * 16) * 2048 + b_row * 64 + b_col;

    float4 ra[2];
    uint4  rwh[2], rwl[2];

    auto ldg_chunk = [&](int i) {
        const float4* ap = (const float4*)(aBase + (size_t)i * 32);
        ra[0] = ap[0];
        ra[1] = ap[1];
        const uint4* wh = (const uint4*)(whBase + i * 2048);
        const uint4* wl = (const uint4*)(wlBase + i * 2048);
        rwh[0] = wh[0]; rwh[1] = wh[1];
        rwl[0] = wl[0]; rwl[1] = wl[1];
    };
    auto sts_chunk = [&](int buf) {
        char* st = sStage[buf];
        uint32_t h0 = cvt_hi2(ra[0].x, ra[0].y);
        uint32_t h1 = cvt_hi2(ra[0].z, ra[0].w);
        uint32_t h2 = cvt_hi2(ra[1].x, ra[1].y);
        uint32_t h3 = cvt_hi2(ra[1].z, ra[1].w);
        uint32_t l0 = cvt_lo2(ra[0].x, ra[0].y, h0);
        uint32_t l1 = cvt_lo2(ra[0].z, ra[0].w, h1);
        uint32_t l2 = cvt_lo2(ra[1].x, ra[1].y, h2);
        uint32_t l3 = cvt_lo2(ra[1].z, ra[1].w, h3);
        uint32_t aoff = (uint32_t)(a_row * APITCH + a_kq) * 2;
        *(uint4*)(st + AHI + aoff) = make_uint4(h0, h1, h2, h3);
        *(uint4*)(st + ALO + aoff) = make_uint4(l0, l1, l2, l3);
        uint32_t boff = (uint32_t)(b_row * BPITCH + b_col) * 2;
        *(uint4*)(st + BHI + boff)      = rwh[0];
        *(uint4*)(st + BHI + boff + 16) = rwh[1];
        *(uint4*)(st + BLO + boff)      = rwl[0];
        *(uint4*)(st + BLO + boff + 16) = rwl[1];
    };

    ldg_chunk(0);
    sts_chunk(0);
    __syncthreads();
    ldg_chunk(1);

    for (int i = 0; i < 16; i++) {
        const int cur = i & 1;
        if (i < 15) sts_chunk(cur ^ 1);
        if (i < 14) ldg_chunk(i + 2);

        const uint32_t sb = smem_u32(sStage[cur]);
#pragma unroll
        for (int kk = 0; kk < 32; kk += 16) {
            uint32_t ah[4], al[4];
            uint32_t ao = sb + AHI + (uint32_t)((wm16 + lkr) * APITCH + kk + lnc) * 2;
            ldsm4(ah[0], ah[1], ah[2], ah[3], ao);
            ldsm4(al[0], al[1], al[2], al[3], ao + (ALO - AHI));

            uint32_t bh[8], bl[8];
            uint32_t bo = sb + BHI + (uint32_t)((kk + lkr) * BPITCH + wn32 + lnc) * 2;
            ldsm4t(bh[0], bh[1], bh[2], bh[3], bo);
            ldsm4t(bh[4], bh[5], bh[6], bh[7], bo + 32);
            ldsm4t(bl[0], bl[1], bl[2], bl[3], bo + (BLO - BHI));
            ldsm4t(bl[4], bl[5], bl[6], bl[7], bo + (BLO - BHI) + 32);
#pragma unroll
            for (int j = 0; j < 4; j++) {
                float* c = acc[j];
                mma_bf16(c, ah, bh[2 * j], bh[2 * j + 1]);   // hi*hi
                mma_bf16(c, ah, bl[2 * j], bl[2 * j + 1]);   // hi*lo
                mma_bf16(c, al, bh[2 * j], bh[2 * j + 1]);   // lo*hi
            }
        }
        __syncthreads();
    }

    // epilogue: plain stores of this split's partial h1
    {
        float* dst = g_h1s[split];
        const int r0 = m_base + wm16 + (lane >> 2);
        const int c0 = (lane & 3) * 2;
#pragma unroll
        for (int j = 0; j < 4; j++) {
            const int n = wn32 + j * 8 + c0;
            dst[r0 * 64 + n]           = acc[j][0];
            dst[r0 * 64 + n + 1]       = acc[j][1];
            dst[(r0 + 8) * 64 + n]     = acc[j][2];
            dst[(r0 + 8) * 64 + n + 1] = acc[j][3];
        }
    }

    // ---- last-block tail: 4th arrival sums partials + runs tail MLP ----
    __threadfence();
    __syncthreads();
    if (tid == 0) sIsLast = (atomicAdd(&g_cnt[mtile], 1) == 3);
    __syncthreads();
    if (!sIsLast) return;
    __threadfence();   // acquire: partials from other blocks now visible

    // stage tail weights into the (dead) stage buffer
    float* sW2 = (float*)sStage[0];            // 1024 floats
    float* sW3 = sW2 + 1024;                   // 128
    float* sW4 = sW3 + 128;                    // 8
    float* sB1 = sW4 + 8;                      // 64
    for (int i = tid; i < 1024; i += 128) sW2[i] = W2[i];
    if (tid < 128) sW3[tid] = W3[tid];
    if (tid < 64)  sB1[tid] = b1[tid];
    if (tid < 8)   sW4[tid] = W4[tid];
    __syncthreads();

    if (tid < 32) {
        const size_t po = (size_t)(m_base + tid) * 64;
        const float4* h0 = (const float4*)(g_h1s[0] + po);
        const float4* h1 = (const float4*)(g_h1s[1] + po);
        const float4* h2p = (const float4*)(g_h1s[2] + po);
        const float4* h3p = (const float4*)(g_h1s[3] + po);

        float h2[16];
#pragma unroll
        for (int j = 0; j < 16; j++) h2[j] = b2[j];
#pragma unroll
        for (int q = 0; q < 16; q++) {
            float4 v0 = h0[q], v1 = h1[q], v2 = h2p[q], v3 = h3p[q];
            float hv0 = fmaxf((v0.x + v1.x) + (v2.x + v3.x) + sB1[q * 4 + 0], 0.f);
            float hv1 = fmaxf((v0.y + v1.y) + (v2.y + v3.y) + sB1[q * 4 + 1], 0.f);
            float hv2 = fmaxf((v0.z + v1.z) + (v2.z + v3.z) + sB1[q * 4 + 2], 0.f);
            float hv3 = fmaxf((v0.w + v1.w) + (v2.w + v3.w) + sB1[q * 4 + 3], 0.f);
#pragma unroll
            for (int j = 0; j < 16; j++) {
                h2[j] += hv0 * sW2[(q * 4 + 0) * 16 + j];
                h2[j] += hv1 * sW2[(q * 4 + 1) * 16 + j];
                h2[j] += hv2 * sW2[(q * 4 + 2) * 16 + j];
                h2[j] += hv3 * sW2[(q * 4 + 3) * 16 + j];
            }
        }
        float h3r[8];
#pragma unroll
        for (int j = 0; j < 8; j++) h3r[j] = b3[j];
#pragma unroll
        for (int n = 0; n < 16; n++) {
            float hvv = fmaxf(h2[n], 0.f);
#pragma unroll
            for (int j = 0; j < 8; j++) h3r[j] += hvv * sW3[n * 8 + j];
        }
        float z = b4[0];
#pragma unroll
        for (int n = 0; n < 8; n++) z += fmaxf(h3r[n], 0.f) * sW4[n];
        g_a[m_base + tid] = 1.f / (1.f + __expf(-z));
    }

    if (tid == 0) g_cnt[mtile] = 0;            // reset for next graph replay
}

// ---------------------------------------------------------------------------
// k2: out[b, c..c+3] += (1/sum_p a) * sum_{p in split} a_p * x[b,p,c..c+3]
// grid 512 = 64 batches x 2 channel halves x 4 pixel splits (49 px each).
// Batch mask-sum computed in-block from g_a (no cross-kernel plumbing).
// ---------------------------------------------------------------------------
__global__ void __launch_bounds__(256) k2_reduce(
    const float* __restrict__ x, float* __restrict__ out)
{
    __shared__ float sa[196];
    __shared__ float swsum[8];
    __shared__ float sinv;
    const int b     = blockIdx.x >> 3;
    const int rem   = blockIdx.x & 7;
    const int half  = rem >> 2;
    const int split = rem & 3;
    const int p0    = split * 49;
    const int t     = threadIdx.x;

    float av = 0.f;
    if (t < 196) { av = g_a[b * 196 + t]; sa[t] = av; }
    float s = av;
#pragma unroll
    for (int o = 16; o; o >>= 1) s += __shfl_down_sync(0xFFFFFFFFu, s, o);
    if ((t & 31) == 0) swsum[t >> 5] = s;
    __syncthreads();
    if (t == 0) {
        float tot = 0.f;
#pragma unroll
        for (int w = 0; w < 8; w++) tot += swsum[w];
        sinv = 1.f / tot;
    }
    __syncthreads();

    const int ch = half * 1024 + t * 4;
    const float4* xp = (const float4*)(x + (size_t)b * 196 * 2048 + (size_t)p0 * 2048 + ch);

    float4 acc = make_float4(0.f, 0.f, 0.f, 0.f);
#pragma unroll 7
    for (int p = 0; p < 49; p++) {
        float ap = sa[p0 + p];
        float4 v = xp[(size_t)p * 512];
        acc.x += ap * v.x;
        acc.y += ap * v.y;
        acc.z += ap * v.z;
        acc.w += ap * v.w;
    }
    const float inv = sinv;
    float* o = out + b * 2048 + ch;
    atomicAdd(o + 0, acc.x * inv);
    atomicAdd(o + 1, acc.y * inv);
    atomicAdd(o + 2, acc.z * inv);
    atomicAdd(o + 3, acc.w * inv);
}

extern "C" void kernel_launch(void* const* d_in, const int* in_sizes, int n_in,
                              void* d_out, int out_size)
{
    const float* x  = (const float*)d_in[0];
    const float* W1 = (const float*)d_in[1];
    const float* b1 = (const float*)d_in[2];
    const float* W2 = (const float*)d_in[3];
    const float* b2 = (const float*)d_in[4];
    const float* W3 = (const float*)d_in[5];
    const float* b3 = (const float*)d_in[6];
    const float* W4 = (const float*)d_in[7];
    const float* b4 = (const float*)d_in[8];
    float* out = (float*)d_out;

    k0_convW<<<640, 256>>>(W1, out);
    k1_gemm<<<1568, 128>>>(x, b1, W2, b2, W3, b3, W4, b4);
    k2_reduce<<<512, 256>>>(x, out);
}

// round 15
// speedup vs baseline: 1.0425x; 1.0425x over previous
#include <cuda_runtime.h>
#include <cuda_bf16.h>
#include <cstdint>

// ---------------------------------------------------------------------------
// Device-global scratch (allocation-free)
// ---------------------------------------------------------------------------
__device__ float g_a[12544];                     // attention scalar per pixel
__device__ float g_invm[64];                     // 1 / sum_p a  per batch
__device__ float g_h1s[4][12544 * 64];           // per-split layer-1 partials
__device__ __align__(16) __nv_bfloat16 gW1hi[64 * 2048];  // [chunk][k32][n64]
__device__ __align__(16) __nv_bfloat16 gW1lo[64 * 2048];

// ---------------------------------------------------------------------------
// Helpers
// ---------------------------------------------------------------------------
__device__ __forceinline__ uint32_t smem_u32(const void* p) {
    return (uint32_t)__cvta_generic_to_shared(p);
}
__device__ __forceinline__ void ldsm4(uint32_t& r0, uint32_t& r1, uint32_t& r2, uint32_t& r3, uint32_t a) {
    asm volatile("ldmatrix.sync.aligned.m8n8.x4.shared.b16 {%0,%1,%2,%3},[%4];"
                 : "=r"(r0), "=r"(r1), "=r"(r2), "=r"(r3) : "r"(a));
}
__device__ __forceinline__ void ldsm4t(uint32_t& r0, uint32_t& r1, uint32_t& r2, uint32_t& r3, uint32_t a) {
    asm volatile("ldmatrix.sync.aligned.m8n8.x4.trans.shared.b16 {%0,%1,%2,%3},[%4];"
                 : "=r"(r0), "=r"(r1), "=r"(r2), "=r"(r3) : "r"(a));
}
__device__ __forceinline__ void mma_bf16(float* c, const uint32_t* a, uint32_t b0, uint32_t b1) {
    asm volatile(
        "mma.sync.aligned.m16n8k16.row.col.f32.bf16.bf16.f32 "
        "{%0,%1,%2,%3},{%4,%5,%6,%7},{%8,%9},{%0,%1,%2,%3};"
        : "+f"(c[0]), "+f"(c[1]), "+f"(c[2]), "+f"(c[3])
        : "r"(a[0]), "r"(a[1]), "r"(a[2]), "r"(a[3]), "r"(b0), "r"(b1));
}
__device__ __forceinline__ uint32_t cvt_hi2(float f0, float f1) {
    uint32_t r;
    asm("cvt.rn.bf16x2.f32 %0, %1, %2;" : "=r"(r) : "f"(f1), "f"(f0));
    return r;
}
__device__ __forceinline__ uint32_t cvt_lo2(float f0, float f1, uint32_t hp) {
    float h0 = __uint_as_float(hp << 16);
    float h1 = __uint_as_float(hp & 0xFFFF0000u);
    return cvt_hi2(f0 - h0, f1 - h1);
}

// ---------------------------------------------------------------------------
// k0: split W1 into bf16 hi/lo in per-chunk staging layout
// ---------------------------------------------------------------------------
__global__ void __launch_bounds__(256) k0_convW(const float* __restrict__ W1) {
    int i = blockIdx.x * 256 + threadIdx.x;       // 131072 elems
    int k = i >> 6, n = i & 63;
    int chunk = k >> 5, kk = k & 31;
    float w = W1[i];
    __nv_bfloat16 h = __float2bfloat16_rn(w);
    int o = chunk * 2048 + kk * 64 + n;
    gW1hi[o] = h;
    gW1lo[o] = __float2bfloat16_rn(w - __bfloat162float(h));
}

// ---------------------------------------------------------------------------
// k1: split-K GEMM.  grid 1568 = 392 m-tiles x 4 K-quarters.
// Tile 32 pixels x 64 outputs, K-chunk 32 (16 chunks per block), 128 threads,
// 4 warps m16 x n32.  Partial h1 stored (plain STG) to per-split buffer.
// ---------------------------------------------------------------------------
#define APITCH 40
#define BPITCH 72
#define AHI 0
#define ALO 2560                  // 32*40*2
#define BHI 5120
#define BLO 9728                  // + 32*72*2
#define STG 14336

__global__ void __launch_bounds__(128) k1_gemm(const float* __restrict__ x)
{
    __shared__ __align__(16) char sStage[2][STG];   // 28672 B

    const int tid  = threadIdx.x;
    const int lane = tid & 31;
    const int warp = tid >> 5;
    const int wm16 = (warp >> 1) * 16;          // 0 or 16
    const int wn32 = (warp & 1) * 32;           // 0 or 32
    const int m_base = (blockIdx.x >> 2) * 32;
    const int split  = blockIdx.x & 3;          // K quarter

    const int lkr = (lane & 7) + ((lane >> 3) & 1) * 8;   // 0..15
    const int lnc = (lane >> 4) * 8;                       // 0 or 8

    const int a_row = tid >> 2;                 // 0..31
    const int a_kq  = (tid & 3) * 8;            // k offset {0,8,16,24}
    const int b_row = tid >> 2;                 // 0..31
    const int b_col = (tid & 3) * 16;           // n offset {0,16,32,48}

    float acc[4][4];
#pragma unroll
    for (int j = 0; j < 4; j++)
#pragma unroll
        for (int i = 0; i < 4; i++) acc[j][i] = 0.f;

    const float* aBase = x + (size_t)(m_base + a_row) * 2048 + split * 512 + a_kq;
    const __nv_bfloat16* whBase = gW1hi + (split * 16) * 2048 + b_row * 64 + b_col;
    const __nv_bfloat16* wlBase = gW1lo + (split * 16) * 2048 + b_row * 64 + b_col;

    float4 ra[2];
    uint4  rwh[2], rwl[2];

    auto ldg_chunk = [&](int i) {
        const float4* ap = (const float4*)(aBase + (size_t)i * 32);
        ra[0] = ap[0];
        ra[1] = ap[1];
        const uint4* wh = (const uint4*)(whBase + i * 2048);
        const uint4* wl = (const uint4*)(wlBase + i * 2048);
        rwh[0] = wh[0]; rwh[1] = wh[1];
        rwl[0] = wl[0]; rwl[1] = wl[1];
    };
    auto sts_chunk = [&](int buf) {
        char* st = sStage[buf];
        uint32_t h0 = cvt_hi2(ra[0].x, ra[0].y);
        uint32_t h1 = cvt_hi2(ra[0].z, ra[0].w);
        uint32_t h2 = cvt_hi2(ra[1].x, ra[1].y);
        uint32_t h3 = cvt_hi2(ra[1].z, ra[1].w);
        uint32_t l0 = cvt_lo2(ra[0].x, ra[0].y, h0);
        uint32_t l1 = cvt_lo2(ra[0].z, ra[0].w, h1);
        uint32_t l2 = cvt_lo2(ra[1].x, ra[1].y, h2);
        uint32_t l3 = cvt_lo2(ra[1].z, ra[1].w, h3);
        uint32_t aoff = (uint32_t)(a_row * APITCH + a_kq) * 2;
        *(uint4*)(st + AHI + aoff) = make_uint4(h0, h1, h2, h3);
        *(uint4*)(st + ALO + aoff) = make_uint4(l0, l1, l2, l3);
        uint32_t boff = (uint32_t)(b_row * BPITCH + b_col) * 2;
        *(uint4*)(st + BHI + boff)      = rwh[0];
        *(uint4*)(st + BHI + boff + 16) = rwh[1];
        *(uint4*)(st + BLO + boff)      = rwl[0];
        *(uint4*)(st + BLO + boff + 16) = rwl[1];
    };

    ldg_chunk(0);
    sts_chunk(0);
    __syncthreads();
    ldg_chunk(1);

    for (int i = 0; i < 16; i++) {
        const int cur = i & 1;
        if (i < 15) sts_chunk(cur ^ 1);
        if (i < 14) ldg_chunk(i + 2);

        const uint32_t sb = smem_u32(sStage[cur]);
#pragma unroll
        for (int kk = 0; kk < 32; kk += 16) {
            uint32_t ah[4], al[4];
            uint32_t ao = sb + AHI + (uint32_t)((wm16 + lkr) * APITCH + kk + lnc) * 2;
            ldsm4(ah[0], ah[1], ah[2], ah[3], ao);
            ldsm4(al[0], al[1], al[2], al[3], ao + (ALO - AHI));

            uint32_t bh[8], bl[8];
            uint32_t bo = sb + BHI + (uint32_t)((kk + lkr) * BPITCH + wn32 + lnc) * 2;
            ldsm4t(bh[0], bh[1], bh[2], bh[3], bo);
            ldsm4t(bh[4], bh[5], bh[6], bh[7], bo + 32);
            ldsm4t(bl[0], bl[1], bl[2], bl[3], bo + (BLO - BHI));
            ldsm4t(bl[4], bl[5], bl[6], bl[7], bo + (BLO - BHI) + 32);
#pragma unroll
            for (int j = 0; j < 4; j++) {
                float* c = acc[j];
                mma_bf16(c, ah, bh[2 * j], bh[2 * j + 1]);   // hi*hi
                mma_bf16(c, ah, bl[2 * j], bl[2 * j + 1]);   // hi*lo
                mma_bf16(c, al, bh[2 * j], bh[2 * j + 1]);   // lo*hi
            }
        }
        __syncthreads();
    }

    // epilogue: plain stores of this split's partial h1
    {
        float* dst = g_h1s[split];
        const int r0 = m_base + wm16 + (lane >> 2);
        const int c0 = (lane & 3) * 2;
#pragma unroll
        for (int j = 0; j < 4; j++) {
            const int n = wn32 + j * 8 + c0;
            dst[r0 * 64 + n]           = acc[j][0];
            dst[r0 * 64 + n + 1]       = acc[j][1];
            dst[(r0 + 8) * 64 + n]     = acc[j][2];
            dst[(r0 + 8) * 64 + n + 1] = acc[j][3];
        }
    }
}

// ---------------------------------------------------------------------------
// k1b: per-batch tail.  grid 64, 224 threads.  Sums the 4 split partials
// (hoisted ahead of weight staging), bias+relu+MLP+sigmoid per pixel,
// write g_a, reduce 1/sum(a) -> g_invm, zero out[b] slice.
// ---------------------------------------------------------------------------
__global__ void __launch_bounds__(224) k1b_tail(
    const float* __restrict__ b1,
    const float* __restrict__ W2, const float* __restrict__ b2,
    const float* __restrict__ W3, const float* __restrict__ b3,
    const float* __restrict__ W4, const float* __restrict__ b4,
    float* __restrict__ out)
{
    __shared__ float sW2[64 * 16];
    __shared__ float sW3[16 * 8];
    __shared__ float sW4[8];
    __shared__ float sB1[64];
    __shared__ float swsum[7];

    const int b = blockIdx.x;
    const int t = threadIdx.x;

    // hoisted h1 loads: sum of 4 split partials (4 independent streams)
    float4 hv[16];
    if (t < 196) {
        const size_t po = (size_t)(b * 196 + t) * 64;
        const float4* h0 = (const float4*)(g_h1s[0] + po);
        const float4* h1 = (const float4*)(g_h1s[1] + po);
        const float4* h2 = (const float4*)(g_h1s[2] + po);
        const float4* h3 = (const float4*)(g_h1s[3] + po);
#pragma unroll
        for (int q = 0; q < 16; q++) {
            float4 v0 = h0[q], v1 = h1[q], v2 = h2[q], v3 = h3[q];
            hv[q] = make_float4((v0.x + v1.x) + (v2.x + v3.x),
                                (v0.y + v1.y) + (v2.y + v3.y),
                                (v0.z + v1.z) + (v2.z + v3.z),
                                (v0.w + v1.w) + (v2.w + v3.w));
        }
    }

    for (int i = t; i < 64 * 16; i += 224) sW2[i] = W2[i];
    if (t < 128) sW3[t] = W3[t];
    if (t < 64)  sB1[t] = b1[t];
    if (t < 8)   sW4[t] = W4[t];
    for (int i = t; i < 2048; i += 224) out[b * 2048 + i] = 0.f;
    __syncthreads();

    float a = 0.f;
    if (t < 196) {
        float h2[16];
#pragma unroll
        for (int j = 0; j < 16; j++) h2[j] = b2[j];
#pragma unroll
        for (int q = 0; q < 16; q++) {
            float4 v = hv[q];
            float hv0 = fmaxf(v.x + sB1[q * 4 + 0], 0.f);
            float hv1 = fmaxf(v.y + sB1[q * 4 + 1], 0.f);
            float hv2 = fmaxf(v.z + sB1[q * 4 + 2], 0.f);
            float hv3 = fmaxf(v.w + sB1[q * 4 + 3], 0.f);
#pragma unroll
            for (int j = 0; j < 16; j++) {
                h2[j] += hv0 * sW2[(q * 4 + 0) * 16 + j];
                h2[j] += hv1 * sW2[(q * 4 + 1) * 16 + j];
                h2[j] += hv2 * sW2[(q * 4 + 2) * 16 + j];
                h2[j] += hv3 * sW2[(q * 4 + 3) * 16 + j];
            }
        }
        float h3r[8];
#pragma unroll
        for (int j = 0; j < 8; j++) h3r[j] = b3[j];
#pragma unroll
        for (int n = 0; n < 16; n++) {
            float hvv = fmaxf(h2[n], 0.f);
#pragma unroll
            for (int j = 0; j < 8; j++) h3r[j] += hvv * sW3[n * 8 + j];
        }
        float z = b4[0];
#pragma unroll
        for (int n = 0; n < 8; n++) z += fmaxf(h3r[n], 0.f) * sW4[n];
        a = 1.f / (1.f + __expf(-z));
        g_a[b * 196 + t] = a;
    }

    // block reduction of sum(a)
    float s = a;
#pragma unroll
    for (int o = 16; o; o >>= 1) s += __shfl_down_sync(0xFFFFFFFFu, s, o);
    if ((t & 31) == 0) swsum[t >> 5] = s;
    __syncthreads();
    if (t == 0) {
        float tot = 0.f;
#pragma unroll
        for (int w = 0; w < 7; w++) tot += swsum[w];
        g_invm[b] = 1.f / tot;
    }
}

// ---------------------------------------------------------------------------
// k2: out[b, c..c+3] += invm[b] * sum_{p in split} a_p * x[b,p,c..c+3]
// grid 896 = 64 batches x 2 channel halves x 7 pixel splits (28 px each).
// float4 loads, 256 threads.
// ---------------------------------------------------------------------------
__global__ void __launch_bounds__(256) k2_reduce(
    const float* __restrict__ x, float* __restrict__ out)
{
    __shared__ float sa[28];
    __shared__ float sinv;
    const int b     = blockIdx.x / 14;
    const int rem   = blockIdx.x % 14;
    const int half  = rem / 7;
    const int split = rem % 7;
    const int p0    = split * 28;

    if (threadIdx.x < 28) sa[threadIdx.x] = g_a[b * 196 + p0 + threadIdx.x];
    if (threadIdx.x == 32) sinv = g_invm[b];
    __syncthreads();

    const int ch = half * 1024 + threadIdx.x * 4;
    const float4* xp = (const float4*)(x + (size_t)b * 196 * 2048 + (size_t)p0 * 2048 + ch);

    float4 acc = make_float4(0.f, 0.f, 0.f, 0.f);
#pragma unroll
    for (int p = 0; p < 28; p++) {
        float ap = sa[p];
        float4 v = xp[(size_t)p * 512];
        acc.x += ap * v.x;
        acc.y += ap * v.y;
        acc.z += ap * v.z;
        acc.w += ap * v.w;
    }
    float* o = out + b * 2048 + ch;
    atomicAdd(o + 0, acc.x * sinv);
    atomicAdd(o + 1, acc.y * sinv);
    atomicAdd(o + 2, acc.z * sinv);
    atomicAdd(o + 3, acc.w * sinv);
}

extern "C" void kernel_launch(void* const* d_in, const int* in_sizes, int n_in,
                              void* d_out, int out_size)
{
    const float* x  = (const float*)d_in[0];
    const float* W1 = (const float*)d_in[1];
    const float* b1 = (const float*)d_in[2];
    const float* W2 = (const float*)d_in[3];
    const float* b2 = (const float*)d_in[4];
    const float* W3 = (const float*)d_in[5];
    const float* b3 = (const float*)d_in[6];
    const float* W4 = (const float*)d_in[7];
    const float* b4 = (const float*)d_in[8];
    float* out = (float*)d_out;

    k0_convW<<<512, 256>>>(W1);
    k1_gemm<<<1568, 128>>>(x);
    k1b_tail<<<64, 224>>>(b1, W2, b2, W3, b3, W4, b4, out);
    k2_reduce<<<896, 256>>>(x, out);
}